// round 1
// baseline (speedup 1.0000x reference)
#include <cuda_runtime.h>
#include <cstdint>

#define DV 128
#define NSTEP 10
#define BSZ 4096
#define CNT0 20000
#define CNT1 2000
#define CNT2 15000
#define ROWS_TOT (CNT0 + CNT1 + CNT2)

typedef unsigned long long u64;

// Scratch (static __device__ arrays: allocation-guard safe)
__device__ __align__(16) float g_P[2 * ROWS_TOT * DV];     // 37.9 MB: precomputed x@Wih^T + biases
__device__ __align__(16) float g_agg[18 * BSZ * DV];       // 37.7 MB: RNN means per (l,set,nt)

static __device__ __forceinline__ u64 pack2(float x, float y){
  u64 r;
  asm("mov.b64 %0, {%1,%2};" : "=l"(r) : "r"(__float_as_uint(x)), "r"(__float_as_uint(y)));
  return r;
}
static __device__ __forceinline__ float2 unpack2(u64 v){
  unsigned lo, hi;
  asm("mov.b64 {%0,%1}, %2;" : "=r"(lo), "=r"(hi) : "l"(v));
  return make_float2(__uint_as_float(lo), __uint_as_float(hi));
}
// Packed dual-fp32 FMA (sm_103a FFMA2) — only reachable via PTX fma.rn.f32x2
static __device__ __forceinline__ void ffma2(u64 &d, u64 a, u64 b){
  asm("fma.rn.f32x2 %0, %1, %2, %0;" : "+l"(d) : "l"(a), "l"(b));
}
// tanh via EX2+RCP: abs error ~1e-7, saturates correctly at +/-inf
static __device__ __forceinline__ float tanh_fast(float x){
  float e = __expf(2.0f * x);
  return 1.0f - __fdividef(2.0f, e + 1.0f);
}

// ---------------------------------------------------------------------------
// Kernel 1: P[l][nt] = emb[nt] @ Wih[l,nt]^T + bih[l,nt] + bhh[l,nt]
// block: 512 threads, 128 rows x 128 cols tile. Wih transposed in smem.
// ---------------------------------------------------------------------------
__global__ void __launch_bounds__(512, 1) precompute_P_kernel(
    const float* __restrict__ emb0, const float* __restrict__ emb1, const float* __restrict__ emb2,
    const float* __restrict__ Wih, const float* __restrict__ bih, const float* __restrict__ bhh)
{
  extern __shared__ float sm[];
  float* Wsh = sm;               // [128][130]  W[k][j] (transposed, stride 130 keeps LDS.64 aligned + conflict-free)
  float* As  = sm + DV * 130;    // [128][33]
  const int tid  = threadIdx.x;
  const int comb = blockIdx.y;   // l*3 + nt
  const int nt   = comb % 3;
  const int l    = comb / 3;
  const int rows = (nt == 0) ? CNT0 : ((nt == 1) ? CNT1 : CNT2);
  const int row0 = blockIdx.x * 128;
  if (row0 >= rows) return;
  const float* emb = (nt == 0) ? emb0 : ((nt == 1) ? emb1 : emb2);
  const float* Wb  = Wih + (size_t)comb * DV * DV;

  for (int idx = tid; idx < DV * DV; idx += 512){
    int j = idx >> 7, k = idx & 127;
    Wsh[k * 130 + j] = Wb[idx];
  }
  __syncthreads();

  const int r0 = (tid >> 4) * 4;        // 4 consecutive rows
  const int jc = (tid & 15) * 2;        // column pairs at jc + 32*p  (conflict-free LDS.64)
  u64 acc[4][4] = {};

  for (int kc = 0; kc < 4; kc++){
    for (int idx = tid; idx < 128 * 32; idx += 512){
      int r = idx >> 5, k = idx & 31;
      int gr = row0 + r;
      As[r * 33 + k] = (gr < rows) ? emb[(size_t)gr * DV + kc * 32 + k] : 0.0f;
    }
    __syncthreads();
    #pragma unroll 4
    for (int k = 0; k < 32; k++){
      const float a0 = As[(r0 + 0) * 33 + k];
      const float a1 = As[(r0 + 1) * 33 + k];
      const float a2 = As[(r0 + 2) * 33 + k];
      const float a3 = As[(r0 + 3) * 33 + k];
      const u64 b0 = pack2(a0, a0), b1 = pack2(a1, a1), b2 = pack2(a2, a2), b3 = pack2(a3, a3);
      const float* wr = &Wsh[(kc * 32 + k) * 130 + jc];
      const u64 w0 = *(const u64*)(wr);
      const u64 w1 = *(const u64*)(wr + 32);
      const u64 w2 = *(const u64*)(wr + 64);
      const u64 w3 = *(const u64*)(wr + 96);
      ffma2(acc[0][0], b0, w0); ffma2(acc[0][1], b0, w1); ffma2(acc[0][2], b0, w2); ffma2(acc[0][3], b0, w3);
      ffma2(acc[1][0], b1, w0); ffma2(acc[1][1], b1, w1); ffma2(acc[1][2], b1, w2); ffma2(acc[1][3], b1, w3);
      ffma2(acc[2][0], b2, w0); ffma2(acc[2][1], b2, w1); ffma2(acc[2][2], b2, w2); ffma2(acc[2][3], b2, w3);
      ffma2(acc[3][0], b3, w0); ffma2(acc[3][1], b3, w1); ffma2(acc[3][2], b3, w2); ffma2(acc[3][3], b3, w3);
    }
    __syncthreads();
  }

  const float* bi = bih + (size_t)comb * DV;
  const float* bh = bhh + (size_t)comb * DV;
  const size_t Poff = (size_t)l * ROWS_TOT * DV
                    + (size_t)((nt == 0) ? 0 : ((nt == 1) ? CNT0 : (CNT0 + CNT1))) * DV;
  #pragma unroll
  for (int i = 0; i < 4; i++){
    int gr = row0 + r0 + i;
    if (gr < rows){
      float* outr = g_P + Poff + (size_t)gr * DV;
      #pragma unroll
      for (int p = 0; p < 4; p++){
        int j = jc + 32 * p;
        float2 a = unpack2(acc[i][p]);
        a.x += bi[j]     + bh[j];
        a.y += bi[j + 1] + bh[j + 1];
        *(float2*)(outr + j) = a;
      }
    }
  }
}

// ---------------------------------------------------------------------------
// Kernel 2: all 18 (layer,set,nt) RNN-mean aggregations.
// block = (combo, 128-row tile). Whh + double-buffered h in smem.
// acc initialized from gathered P rows -> p-load latency hidden under matmul.
// ---------------------------------------------------------------------------
__global__ void __launch_bounds__(512, 1) rnn_agg_kernel(
    const float* __restrict__ Whh,
    const int* __restrict__ c_ids, const int* __restrict__ pos_ids, const int* __restrict__ neg_ids,
    const int* __restrict__ n00, const int* __restrict__ n01, const int* __restrict__ n02,
    const int* __restrict__ n10, const int* __restrict__ n11, const int* __restrict__ n12)
{
  extern __shared__ float sm[];
  float* Wsh   = sm;                       // [128][130]
  float* hA    = sm + DV * 130;            // [128][132]  (stride 132 -> 16B-aligned float4 rows)
  float* hB    = hA + DV * 132;            // [128][132]
  int*   nidsh = (int*)(hB + DV * 132);    // [128][10]

  const int tid = threadIdx.x;
  const int y   = blockIdx.y;              // l*9 + set*3 + nt
  const int l   = y / 9;
  const int rem = y % 9;
  const int set = rem / 3;
  const int nt  = rem % 3;
  const int ntype = (set == 0) ? 0 : 1;
  const int* ids = (set == 0) ? c_ids : ((set == 1) ? pos_ids : neg_ids);
  const int nsel = ntype * 3 + nt;
  const int* ntab = (nsel == 0) ? n00 : (nsel == 1) ? n01 : (nsel == 2) ? n02
                  : (nsel == 3) ? n10 : (nsel == 4) ? n11 : n12;
  const float* Wb = Whh + (size_t)(l * 3 + nt) * DV * DV;
  const float* Pb = g_P + (size_t)l * ROWS_TOT * DV
                  + (size_t)((nt == 0) ? 0 : ((nt == 1) ? CNT0 : (CNT0 + CNT1))) * DV;
  const int row0 = blockIdx.x * 128;

  for (int idx = tid; idx < DV * DV; idx += 512){
    int j = idx >> 7, k = idx & 127;
    Wsh[k * 130 + j] = Wb[idx];
  }
  for (int idx = tid; idx < 128 * NSTEP; idx += 512){
    int r = idx / NSTEP, s = idx % NSTEP;
    nidsh[idx] = ntab[(size_t)ids[row0 + r] * NSTEP + s];
  }
  __syncthreads();

  const int r0 = (tid >> 4) * 4;
  const int jc = (tid & 15) * 2;
  float2 hsum[4][4];
  #pragma unroll
  for (int i = 0; i < 4; i++)
    #pragma unroll
    for (int p = 0; p < 4; p++) hsum[i][p] = make_float2(0.0f, 0.0f);

  for (int s = 0; s < NSTEP; s++){
    float* rd  = (s & 1) ? hA : hB;   // written at step s-1
    float* wr_ = (s & 1) ? hB : hA;   // written this step (== rd of s-1, reads drained at prior sync)

    // acc <- gathered P rows (issues LDGs early; latency hidden under matmul)
    u64 acc[4][4];
    int nv[4];
    #pragma unroll
    for (int i = 0; i < 4; i++) nv[i] = nidsh[(r0 + i) * NSTEP + s];
    #pragma unroll
    for (int i = 0; i < 4; i++){
      const float* prow = Pb + (size_t)nv[i] * DV;
      #pragma unroll
      for (int p = 0; p < 4; p++)
        acc[i][p] = *(const u64*)(prow + jc + 32 * p);
    }

    if (s > 0){
      #pragma unroll 2
      for (int k = 0; k < DV; k += 4){
        float4 h0 = *(const float4*)&rd[(r0 + 0) * 132 + k];
        float4 h1 = *(const float4*)&rd[(r0 + 1) * 132 + k];
        float4 h2 = *(const float4*)&rd[(r0 + 2) * 132 + k];
        float4 h3 = *(const float4*)&rd[(r0 + 3) * 132 + k];
        const float* hp0 = (const float*)&h0;
        const float* hp1 = (const float*)&h1;
        const float* hp2 = (const float*)&h2;
        const float* hp3 = (const float*)&h3;
        #pragma unroll
        for (int kk = 0; kk < 4; kk++){
          const float* wrow = &Wsh[(k + kk) * 130 + jc];
          const u64 w0 = *(const u64*)(wrow);
          const u64 w1 = *(const u64*)(wrow + 32);
          const u64 w2 = *(const u64*)(wrow + 64);
          const u64 w3 = *(const u64*)(wrow + 96);
          const u64 b0 = pack2(hp0[kk], hp0[kk]);
          const u64 b1 = pack2(hp1[kk], hp1[kk]);
          const u64 b2 = pack2(hp2[kk], hp2[kk]);
          const u64 b3 = pack2(hp3[kk], hp3[kk]);
          ffma2(acc[0][0], b0, w0); ffma2(acc[0][1], b0, w1); ffma2(acc[0][2], b0, w2); ffma2(acc[0][3], b0, w3);
          ffma2(acc[1][0], b1, w0); ffma2(acc[1][1], b1, w1); ffma2(acc[1][2], b1, w2); ffma2(acc[1][3], b1, w3);
          ffma2(acc[2][0], b2, w0); ffma2(acc[2][1], b2, w1); ffma2(acc[2][2], b2, w2); ffma2(acc[2][3], b2, w3);
          ffma2(acc[3][0], b3, w0); ffma2(acc[3][1], b3, w1); ffma2(acc[3][2], b3, w2); ffma2(acc[3][3], b3, w3);
        }
      }
    }

    #pragma unroll
    for (int i = 0; i < 4; i++){
      #pragma unroll
      for (int p = 0; p < 4; p++){
        float2 a = unpack2(acc[i][p]);
        float hx = tanh_fast(a.x);
        float hy = tanh_fast(a.y);
        hsum[i][p].x += hx; hsum[i][p].y += hy;
        *(float2*)&wr_[(r0 + i) * 132 + jc + 32 * p] = make_float2(hx, hy);
      }
    }
    __syncthreads();
  }

  float* ob = g_agg + ((size_t)y * BSZ + row0) * DV;
  const float inv = 1.0f / NSTEP;
  #pragma unroll
  for (int i = 0; i < 4; i++){
    #pragma unroll
    for (int p = 0; p < 4; p++)
      *(float2*)&ob[(r0 + i) * DV + jc + 32 * p] =
          make_float2(hsum[i][p].x * inv, hsum[i][p].y * inv);
  }
}

// ---------------------------------------------------------------------------
// Kernel 3: attention over [cur, agg0, agg1, agg2], 2 layers, leaky-relu.
// ---------------------------------------------------------------------------
static __device__ __forceinline__ float breduce128(float v, float* sh){
  #pragma unroll
  for (int o = 16; o > 0; o >>= 1) v += __shfl_xor_sync(0xffffffffu, v, o);
  if ((threadIdx.x & 31) == 0) sh[threadIdx.x >> 5] = v;
  __syncthreads();
  float r = sh[0] + sh[1] + sh[2] + sh[3];
  __syncthreads();
  return r;
}

__global__ void __launch_bounds__(128) attn_kernel(
    const float* __restrict__ emb0, const float* __restrict__ emb1,
    const int* __restrict__ c_ids, const int* __restrict__ pos_ids, const int* __restrict__ neg_ids,
    const float* __restrict__ attW, float* __restrict__ out)
{
  __shared__ float sh[4];
  const int b   = blockIdx.x;
  const int set = blockIdx.y;
  const int d   = threadIdx.x;
  const int ntype = (set == 0) ? 0 : 1;
  const int* ids = (set == 0) ? c_ids : ((set == 1) ? pos_ids : neg_ids);
  const float* emb = (ntype == 0) ? emb0 : emb1;
  const int id = ids[b];
  float cur = emb[(size_t)id * DV + d];

  #pragma unroll
  for (int l = 0; l < 2; l++){
    const float* aw = attW + (size_t)(l * 3 + ntype) * 2 * DV;
    float awc = aw[d];
    float awn = aw[DV + d];
    float st0 = g_agg[((size_t)(l * 9 + set * 3 + 0) * BSZ + b) * DV + d];
    float st1 = g_agg[((size_t)(l * 9 + set * 3 + 1) * BSZ + b) * DV + d];
    float st2 = g_agg[((size_t)(l * 9 + set * 3 + 2) * BSZ + b) * DV + d];
    float base = breduce128(cur * awc, sh);
    float s0 = base + breduce128(cur * awn, sh);
    float s1 = base + breduce128(st0 * awn, sh);
    float s2 = base + breduce128(st1 * awn, sh);
    float s3 = base + breduce128(st2 * awn, sh);
    float m = fmaxf(fmaxf(s0, s1), fmaxf(s2, s3));
    float e0 = expf(s0 - m), e1 = expf(s1 - m), e2 = expf(s2 - m), e3 = expf(s3 - m);
    float inv = 1.0f / (e0 + e1 + e2 + e3);
    float v = (e0 * cur + e1 * st0 + e2 * st1 + e3 * st2) * inv;
    cur = (v > 0.0f) ? v : 0.01f * v;
  }
  out[((size_t)set * BSZ + b) * DV + d] = cur;
}

// ---------------------------------------------------------------------------
extern "C" void kernel_launch(void* const* d_in, const int* in_sizes, int n_in,
                              void* d_out, int out_size)
{
  const int*   c_ids   = (const int*)d_in[0];
  const int*   pos_ids = (const int*)d_in[1];
  const int*   neg_ids = (const int*)d_in[2];
  const int*   n00 = (const int*)d_in[3];
  const int*   n01 = (const int*)d_in[4];
  const int*   n02 = (const int*)d_in[5];
  const int*   n10 = (const int*)d_in[6];
  const int*   n11 = (const int*)d_in[7];
  const int*   n12 = (const int*)d_in[8];
  // d_in[9..11] = neigh_s2_* (unused: triple sets are types 0 and 1 only)
  const float* emb0 = (const float*)d_in[12];
  const float* emb1 = (const float*)d_in[13];
  const float* emb2 = (const float*)d_in[14];
  const float* Wih  = (const float*)d_in[15];
  const float* Whh  = (const float*)d_in[16];
  const float* bih  = (const float*)d_in[17];
  const float* bhh  = (const float*)d_in[18];
  const float* attW = (const float*)d_in[19];

  const int smemP = (DV * 130 + 128 * 33) * (int)sizeof(float);                         // 83,456 B
  const int smemR = (DV * 130 + 2 * DV * 132) * (int)sizeof(float)
                  + 128 * NSTEP * (int)sizeof(int);                                     // 206,848 B
  cudaFuncSetAttribute(precompute_P_kernel, cudaFuncAttributeMaxDynamicSharedMemorySize, smemP);
  cudaFuncSetAttribute(rnn_agg_kernel,      cudaFuncAttributeMaxDynamicSharedMemorySize, smemR);

  precompute_P_kernel<<<dim3(157, 6), 512, smemP>>>(emb0, emb1, emb2, Wih, bih, bhh);
  rnn_agg_kernel<<<dim3(BSZ / 128, 18), 512, smemR>>>(Whh, c_ids, pos_ids, neg_ids,
                                                      n00, n01, n02, n10, n11, n12);
  attn_kernel<<<dim3(BSZ, 3), 128>>>(emb0, emb1, c_ids, pos_ids, neg_ids, attW, (float*)d_out);
}